// round 1
// baseline (speedup 1.0000x reference)
#include <cuda_runtime.h>

#define BATCH 65536
#define CEN   10
#define DIM   384
#define HID   768
#define D4    96            // DIM/4

#define PHI_OFF ((size_t)BATCH * DIM)
#define TGT_OFF ((size_t)BATCH * DIM + (size_t)BATCH * CEN)

__device__ float g_center[CEN * DIM];
__device__ float g_colsum[CEN];

// ---------------------------------------------------------------------------
// K1: Center = leaky_relu(M @ W1 + b1) / 384 ; also zero colsum accumulator.
// grid 30 x 128: blockIdx -> (c, d-chunk of 128)
// ---------------------------------------------------------------------------
__global__ void k_center(const float* __restrict__ M,
                         const float* __restrict__ W1,
                         const float* __restrict__ b1) {
    int c = blockIdx.x / 3;
    int d = (blockIdx.x % 3) * 128 + threadIdx.x;
    const float* Mrow = M + c * HID;
    float a0 = 0.f, a1 = 0.f, a2 = 0.f, a3 = 0.f;
#pragma unroll 4
    for (int h = 0; h < HID; h += 4) {
        a0 += __ldg(Mrow + h + 0) * __ldg(W1 + (h + 0) * DIM + d);
        a1 += __ldg(Mrow + h + 1) * __ldg(W1 + (h + 1) * DIM + d);
        a2 += __ldg(Mrow + h + 2) * __ldg(W1 + (h + 2) * DIM + d);
        a3 += __ldg(Mrow + h + 3) * __ldg(W1 + (h + 3) * DIM + d);
    }
    float v = (a0 + a1) + (a2 + a3) + __ldg(b1 + d);
    v = (v >= 0.f) ? v : 0.01f * v;
    g_center[c * DIM + d] = v * (1.0f / 384.0f);
    if (blockIdx.x == 0 && threadIdx.x < CEN) g_colsum[threadIdx.x] = 0.f;
}

// ---------------------------------------------------------------------------
// K2: phi[b][c] = (1/(1+||z_b - c||^2)) / sum_c(...)  + colsum accumulation.
// Warp-per-2-rows, lane owns 12 d's (3x float4, stride-32 pattern).
// ||z-c||^2 = zz - 2*(z.c) + cc  -> one FMA per element.
// ---------------------------------------------------------------------------
__global__ __launch_bounds__(256, 2)
void k_phi(const float* __restrict__ Ztd, float* __restrict__ out) {
    __shared__ float4 sC[CEN * D4];
    __shared__ float  scn[CEN];
    __shared__ float  sred[8][CEN];

    int tid = threadIdx.x, lane = tid & 31, wid = tid >> 5;

    const float4* gc4 = (const float4*)g_center;
    for (int i = tid; i < CEN * D4; i += 256) sC[i] = gc4[i];
    __syncthreads();

    // per-block center norms ||c||^2
    for (int c = wid; c < CEN; c += 8) {
        float s = 0.f;
#pragma unroll
        for (int k = 0; k < 3; k++) {
            float4 v = sC[c * D4 + lane + 32 * k];
            s += v.x * v.x + v.y * v.y + v.z * v.z + v.w * v.w;
        }
#pragma unroll
        for (int o = 16; o; o >>= 1) s += __shfl_xor_sync(0xffffffffu, s, o);
        if (lane == 0) scn[c] = s;
    }
    __syncthreads();

    float cn[CEN];
#pragma unroll
    for (int c = 0; c < CEN; c++) cn[c] = scn[c];
    float colAcc[CEN];
#pragma unroll
    for (int c = 0; c < CEN; c++) colAcc[c] = 0.f;

    const float4* Z4 = (const float4*)Ztd;
    float* phiOut = out + PHI_OFF;

    int gw = blockIdx.x * 8 + wid;
    int nw = gridDim.x * 8;
    for (int g = gw; g < BATCH / 2; g += nw) {
        int row0 = 2 * g;
        float4 z0[3], z1[3];
#pragma unroll
        for (int k = 0; k < 3; k++) {
            z0[k] = Z4[(size_t)row0 * D4 + lane + 32 * k];
            z1[k] = Z4[(size_t)(row0 + 1) * D4 + lane + 32 * k];
        }
        float zz0 = 0.f, zz1 = 0.f;
#pragma unroll
        for (int k = 0; k < 3; k++) {
            zz0 += z0[k].x * z0[k].x + z0[k].y * z0[k].y + z0[k].z * z0[k].z + z0[k].w * z0[k].w;
            zz1 += z1[k].x * z1[k].x + z1[k].y * z1[k].y + z1[k].z * z1[k].z + z1[k].w * z1[k].w;
        }
        float dp0[CEN], dp1[CEN];
#pragma unroll
        for (int c = 0; c < CEN; c++) {
            float a0 = 0.f, a1 = 0.f;
#pragma unroll
            for (int k = 0; k < 3; k++) {
                float4 cv = sC[c * D4 + lane + 32 * k];
                a0 += z0[k].x * cv.x + z0[k].y * cv.y + z0[k].z * cv.z + z0[k].w * cv.w;
                a1 += z1[k].x * cv.x + z1[k].y * cv.y + z1[k].z * cv.z + z1[k].w * cv.w;
            }
            dp0[c] = a0; dp1[c] = a1;
        }
        // butterfly reduce all 22 partials (all lanes end with full sums)
#pragma unroll
        for (int o = 16; o; o >>= 1) {
            zz0 += __shfl_xor_sync(0xffffffffu, zz0, o);
            zz1 += __shfl_xor_sync(0xffffffffu, zz1, o);
#pragma unroll
            for (int c = 0; c < CEN; c++) {
                dp0[c] += __shfl_xor_sync(0xffffffffu, dp0[c], o);
                dp1[c] += __shfl_xor_sync(0xffffffffu, dp1[c], o);
            }
        }
        float nu0[CEN], nu1[CEN], den0 = 0.f, den1 = 0.f;
#pragma unroll
        for (int c = 0; c < CEN; c++) {
            float n0 = zz0 - 2.f * dp0[c] + cn[c];
            float n1 = zz1 - 2.f * dp1[c] + cn[c];
            nu0[c] = __fdividef(1.f, 1.f + n0); den0 += nu0[c];
            nu1[c] = __fdividef(1.f, 1.f + n1); den1 += nu1[c];
        }
        float i0 = __fdividef(1.f, den0), i1 = __fdividef(1.f, den1);
        float p0 = 0.f, p1 = 0.f;
#pragma unroll
        for (int c = 0; c < CEN; c++) {
            float ph0 = nu0[c] * i0;
            float ph1 = nu1[c] * i1;
            colAcc[c] += ph0 + ph1;
            if (lane == c) { p0 = ph0; p1 = ph1; }
        }
        if (lane < CEN) {
            phiOut[(size_t)row0 * CEN + lane]       = p0;
            phiOut[(size_t)(row0 + 1) * CEN + lane] = p1;
        }
    }

    // block-level colsum reduce -> one atomicAdd per center per block
    if (lane == 0) {
#pragma unroll
        for (int c = 0; c < CEN; c++) sred[wid][c] = colAcc[c];
    }
    __syncthreads();
    if (tid < CEN) {
        float s = 0.f;
#pragma unroll
        for (int w = 0; w < 8; w++) s += sred[w][tid];
        atomicAdd(&g_colsum[tid], s);
    }
}

// ---------------------------------------------------------------------------
// K3: ct = phi @ Center  (weighted) or Center[argmax(phi)] (hard).
// block = 96 threads; thread owns one float4 column of Center (all 10 rows in regs).
// ---------------------------------------------------------------------------
__global__ void k_ct(float* __restrict__ out, const int* __restrict__ weighted) {
    int d4 = threadIdx.x;   // 0..95
    float4 cv[CEN];
    const float4* gc4 = (const float4*)g_center;
#pragma unroll
    for (int c = 0; c < CEN; c++) cv[c] = gc4[c * D4 + d4];

    const float* phi = out + PHI_OFF;
    float4* ct4 = (float4*)out;
    int w = *weighted;

    for (int row = blockIdx.x; row < BATCH; row += gridDim.x) {
        const float2* p2 = (const float2*)(phi + (size_t)row * CEN);
        float ph[CEN];
        float2 t;
        t = __ldg(p2 + 0); ph[0] = t.x; ph[1] = t.y;
        t = __ldg(p2 + 1); ph[2] = t.x; ph[3] = t.y;
        t = __ldg(p2 + 2); ph[4] = t.x; ph[5] = t.y;
        t = __ldg(p2 + 3); ph[6] = t.x; ph[7] = t.y;
        t = __ldg(p2 + 4); ph[8] = t.x; ph[9] = t.y;

        float4 acc;
        if (w) {
            acc.x = acc.y = acc.z = acc.w = 0.f;
#pragma unroll
            for (int c = 0; c < CEN; c++) {
                acc.x += ph[c] * cv[c].x;
                acc.y += ph[c] * cv[c].y;
                acc.z += ph[c] * cv[c].z;
                acc.w += ph[c] * cv[c].w;
            }
        } else {
            int am = 0; float bm = ph[0];
#pragma unroll
            for (int c = 1; c < CEN; c++) {
                if (ph[c] > bm) { bm = ph[c]; am = c; }
            }
            acc = cv[0];
#pragma unroll
            for (int c = 1; c < CEN; c++) {
                if (am == c) acc = cv[c];
            }
        }
        ct4[(size_t)row * D4 + d4] = acc;
    }
}

// ---------------------------------------------------------------------------
// K4: cluster_target: w = phi^2/(colsum+1e-9), row-normalized. Thread per row.
// ---------------------------------------------------------------------------
__global__ void k_target(float* __restrict__ out) {
    int row = blockIdx.x * 256 + threadIdx.x;
    if (row >= BATCH) return;
    const float* phi = out + PHI_OFF;
    float* tgt = out + TGT_OFF;

    float cs[CEN];
#pragma unroll
    for (int c = 0; c < CEN; c++) cs[c] = g_colsum[c] + 1e-9f;

    const float2* p2 = (const float2*)(phi + (size_t)row * CEN);
    float ph[CEN];
    float2 t;
    t = p2[0]; ph[0] = t.x; ph[1] = t.y;
    t = p2[1]; ph[2] = t.x; ph[3] = t.y;
    t = p2[2]; ph[4] = t.x; ph[5] = t.y;
    t = p2[3]; ph[6] = t.x; ph[7] = t.y;
    t = p2[4]; ph[8] = t.x; ph[9] = t.y;

    float wv[CEN], s = 0.f;
#pragma unroll
    for (int c = 0; c < CEN; c++) {
        wv[c] = __fdividef(ph[c] * ph[c], cs[c]);
        s += wv[c];
    }
    float inv = __fdividef(1.f, s);
    float2* o2 = (float2*)(tgt + (size_t)row * CEN);
    float2 r;
    r.x = wv[0] * inv; r.y = wv[1] * inv; o2[0] = r;
    r.x = wv[2] * inv; r.y = wv[3] * inv; o2[1] = r;
    r.x = wv[4] * inv; r.y = wv[5] * inv; o2[2] = r;
    r.x = wv[6] * inv; r.y = wv[7] * inv; o2[3] = r;
    r.x = wv[8] * inv; r.y = wv[9] * inv; o2[4] = r;
}

// ---------------------------------------------------------------------------
extern "C" void kernel_launch(void* const* d_in, const int* in_sizes, int n_in,
                              void* d_out, int out_size) {
    const float* Ztd = (const float*)d_in[0];
    const float* M   = (const float*)d_in[1];
    const float* W1  = (const float*)d_in[2];
    const float* b1  = (const float*)d_in[3];
    const int*   wfl = (const int*)d_in[4];
    float* out = (float*)d_out;

    k_center<<<30, 128>>>(M, W1, b1);
    k_phi<<<2048, 256>>>(Ztd, out);
    k_ct<<<2048, 96>>>(out, wfl);
    k_target<<<256, 256>>>(out);
}

// round 2
// speedup vs baseline: 2.4980x; 2.4980x over previous
#include <cuda_runtime.h>

#define BATCH 65536
#define CEN   10
#define DIM   384
#define HID   768
#define D4    96

#define PHI_OFF ((size_t)BATCH * DIM)
#define TGT_OFF ((size_t)BATCH * DIM + (size_t)BATCH * CEN)

__device__ float g_center[CEN * DIM];
__device__ float g_colsum[CEN];

// ---------------------------------------------------------------------------
// K1: Center = leaky_relu(M @ W1 + b1)/384, spread over 120 blocks.
// block b: center c=b/12, d-chunk=(b%12)*32. 128 threads = 4 h-splits x 32 d.
// ---------------------------------------------------------------------------
__global__ void k_center(const float* __restrict__ M,
                         const float* __restrict__ W1,
                         const float* __restrict__ b1) {
    int c     = blockIdx.x / 12;
    int chunk = blockIdx.x % 12;
    int lane  = threadIdx.x & 31;
    int s     = threadIdx.x >> 5;        // h-split 0..3
    int d     = chunk * 32 + lane;
    const float* Mrow = M + c * HID;
    int h0 = s * 192;
    float acc = 0.f;
#pragma unroll 8
    for (int h = 0; h < 192; h++) {
        acc += __ldg(Mrow + h0 + h) * __ldg(W1 + (size_t)(h0 + h) * DIM + d);
    }
    __shared__ float sred[4][32];
    sred[s][lane] = acc;
    __syncthreads();
    if (threadIdx.x < 32) {
        float v = sred[0][lane] + sred[1][lane] + sred[2][lane] + sred[3][lane]
                + __ldg(b1 + d);
        v = (v >= 0.f) ? v : 0.01f * v;
        g_center[c * DIM + d] = v * (1.0f / 384.0f);
    }
    if (blockIdx.x == 0 && threadIdx.x < CEN) g_colsum[threadIdx.x] = 0.f;
}

// ---------------------------------------------------------------------------
// K2 (fused): phi + ct + colsum in one pass.
// 256 threads = 8 warps; warp = 8 groups of 4 lanes; group owns one row.
// Lane q of a group covers d4 = k*4+q (k=0..23) -> 96 floats of the row.
// ||z-c||^2 = zz - 2 z.c + cc; 2-level butterfly over 4 lanes only.
// ct = sum_c phi_c * C[c][:] written straight from the same lane partition.
// grid 1024 -> 64 rows/block, exactly one pass (65536 rows total).
// ---------------------------------------------------------------------------
__global__ __launch_bounds__(256)
void k_fused(const float* __restrict__ Ztd, float* __restrict__ out,
             const int* __restrict__ weighted) {
    __shared__ float4 sC[CEN * D4];
    __shared__ float  scn[CEN];
    __shared__ float  sred[8][CEN];

    int tid = threadIdx.x, lane = tid & 31, wid = tid >> 5;
    int q = lane & 3;                    // quarter within group
    int g = lane >> 2;                   // group (row) within warp

    const float4* gc4 = (const float4*)g_center;
    for (int i = tid; i < CEN * D4; i += 256) sC[i] = gc4[i];
    __syncthreads();

    // per-block center norms ||c||^2 (lane-parallel, 3 float4 per lane)
    for (int c = wid; c < CEN; c += 8) {
        float s = 0.f;
#pragma unroll
        for (int k = 0; k < 3; k++) {
            float4 v = sC[c * D4 + lane + 32 * k];
            s += v.x * v.x + v.y * v.y + v.z * v.z + v.w * v.w;
        }
#pragma unroll
        for (int o = 16; o; o >>= 1) s += __shfl_xor_sync(0xffffffffu, s, o);
        if (lane == 0) scn[c] = s;
    }
    __syncthreads();

    int row = blockIdx.x * 64 + wid * 8 + g;
    const float4* Z4 = (const float4*)Ztd;
    size_t zbase = (size_t)row * D4 + q;

    float dp[CEN];
#pragma unroll
    for (int c = 0; c < CEN; c++) dp[c] = 0.f;
    float zz = 0.f;

#pragma unroll 4
    for (int k = 0; k < 24; k++) {
        float4 z = __ldcs(&Z4[zbase + k * 4]);
        zz += z.x * z.x + z.y * z.y + z.z * z.z + z.w * z.w;
#pragma unroll
        for (int c = 0; c < CEN; c++) {
            float4 cv = sC[c * D4 + k * 4 + q];
            dp[c] += z.x * cv.x + z.y * cv.y + z.z * cv.z + z.w * cv.w;
        }
    }

    // reduce across the 4 lanes of the group (all 4 end with full sums)
#pragma unroll
    for (int o = 1; o <= 2; o <<= 1) {
        zz += __shfl_xor_sync(0xffffffffu, zz, o);
#pragma unroll
        for (int c = 0; c < CEN; c++)
            dp[c] += __shfl_xor_sync(0xffffffffu, dp[c], o);
    }

    float nu[CEN], den = 0.f;
#pragma unroll
    for (int c = 0; c < CEN; c++) {
        float n = zz - 2.f * dp[c] + scn[c];
        nu[c] = __fdividef(1.f, 1.f + n);
        den += nu[c];
    }
    float inv = __fdividef(1.f, den);
    float phi[CEN];
#pragma unroll
    for (int c = 0; c < CEN; c++) phi[c] = nu[c] * inv;

    // write phi row (40B): lanes q=0..3 write float2 slots 0..3, q0 also slot 4
    {
        float2* p2 = (float2*)(out + PHI_OFF + (size_t)row * CEN);
        p2[q] = make_float2(phi[2 * q], phi[2 * q + 1]);
        if (q == 0) p2[4] = make_float2(phi[8], phi[9]);
    }

    // ct for this lane's 96-float segment
    float4* ct4 = (float4*)out;
    int w = *weighted;
    if (w) {
#pragma unroll 4
        for (int k = 0; k < 24; k++) {
            float4 a = make_float4(0.f, 0.f, 0.f, 0.f);
#pragma unroll
            for (int c = 0; c < CEN; c++) {
                float4 cv = sC[c * D4 + k * 4 + q];
                a.x += phi[c] * cv.x;
                a.y += phi[c] * cv.y;
                a.z += phi[c] * cv.z;
                a.w += phi[c] * cv.w;
            }
            __stcs(&ct4[zbase + k * 4], a);
        }
    } else {
        int am = 0; float bm = phi[0];
#pragma unroll
        for (int c = 1; c < CEN; c++)
            if (phi[c] > bm) { bm = phi[c]; am = c; }
#pragma unroll 4
        for (int k = 0; k < 24; k++)
            __stcs(&ct4[zbase + k * 4], sC[am * D4 + k * 4 + q]);
    }

    // colsum: fold groups together (all lanes of a group hold identical phi)
#pragma unroll
    for (int o = 4; o <= 16; o <<= 1) {
#pragma unroll
        for (int c = 0; c < CEN; c++)
            phi[c] += __shfl_xor_sync(0xffffffffu, phi[c], o);
    }
    if (lane == 0) {
#pragma unroll
        for (int c = 0; c < CEN; c++) sred[wid][c] = phi[c];
    }
    __syncthreads();
    if (tid < CEN) {
        float s = 0.f;
#pragma unroll
        for (int wv = 0; wv < 8; wv++) s += sred[wv][tid];
        atomicAdd(&g_colsum[tid], s);
    }
}

// ---------------------------------------------------------------------------
// K3: cluster_target. Thread per 2 rows -> float4 I/O (80B in, 80B out).
// ---------------------------------------------------------------------------
__global__ void k_target(float* __restrict__ out) {
    int t = blockIdx.x * 256 + threadIdx.x;     // 0..32767
    if (t >= BATCH / 2) return;

    float cs[CEN];
#pragma unroll
    for (int c = 0; c < CEN; c++) cs[c] = g_colsum[c] + 1e-9f;

    const float4* p4 = (const float4*)(out + PHI_OFF + (size_t)t * 2 * CEN);
    float4 v[5];
#pragma unroll
    for (int i = 0; i < 5; i++) v[i] = __ldg(&p4[i]);
    float ph[20];
#pragma unroll
    for (int i = 0; i < 5; i++) {
        ph[4 * i + 0] = v[i].x; ph[4 * i + 1] = v[i].y;
        ph[4 * i + 2] = v[i].z; ph[4 * i + 3] = v[i].w;
    }

    float wv[20];
    float s0 = 0.f, s1 = 0.f;
#pragma unroll
    for (int c = 0; c < CEN; c++) {
        wv[c] = __fdividef(ph[c] * ph[c], cs[c]);
        s0 += wv[c];
        wv[10 + c] = __fdividef(ph[10 + c] * ph[10 + c], cs[c]);
        s1 += wv[10 + c];
    }
    float i0 = __fdividef(1.f, s0), i1 = __fdividef(1.f, s1);
#pragma unroll
    for (int c = 0; c < CEN; c++) { wv[c] *= i0; wv[10 + c] *= i1; }

    float4* o4 = (float4*)(out + TGT_OFF + (size_t)t * 2 * CEN);
#pragma unroll
    for (int i = 0; i < 5; i++)
        o4[i] = make_float4(wv[4 * i], wv[4 * i + 1], wv[4 * i + 2], wv[4 * i + 3]);
}

// ---------------------------------------------------------------------------
extern "C" void kernel_launch(void* const* d_in, const int* in_sizes, int n_in,
                              void* d_out, int out_size) {
    const float* Ztd = (const float*)d_in[0];
    const float* M   = (const float*)d_in[1];
    const float* W1  = (const float*)d_in[2];
    const float* b1  = (const float*)d_in[3];
    const int*   wfl = (const int*)d_in[4];
    float* out = (float*)d_out;

    k_center<<<120, 128>>>(M, W1, b1);
    k_fused<<<1024, 256>>>(Ztd, out, wfl);
    k_target<<<128, 256>>>(out);
}

// round 3
// speedup vs baseline: 2.7407x; 1.0972x over previous
#include <cuda_runtime.h>

#define BATCH 65536
#define CEN   10
#define DIM   384
#define HID   768
#define D4    96

#define PHI_OFF ((size_t)BATCH * DIM)
#define TGT_OFF ((size_t)BATCH * DIM + (size_t)BATCH * CEN)

__device__ float  g_center[CEN * DIM];
__device__ float  g_colsum[CEN];
__device__ float4 g_part4[24 * CEN * D4];   // split-K partials for center GEMM

// packed f32x2 helpers (FFMA2 path — not reachable from plain C++)
#define FMA2(d, a, b, c_) \
    asm("fma.rn.f32x2 %0, %1, %2, %3;" : "=l"(d) : "l"(a), "l"(b), "l"(c_))
__device__ __forceinline__ unsigned long long pk2(float a, float b) {
    unsigned long long r;
    asm("mov.b64 %0, {%1, %2};" : "=l"(r) : "f"(a), "f"(b));
    return r;
}
__device__ __forceinline__ float upk_sum(unsigned long long v) {
    float lo, hi;
    asm("mov.b64 {%0, %1}, %2;" : "=f"(lo), "=f"(hi) : "l"(v));
    return lo + hi;
}

// ---------------------------------------------------------------------------
// K1a: split-K partial GEMM. 24 blocks x 384 threads (4 h-splits x 96 d4).
// Block b covers h in [b*32, b*32+32); h-split covers 8 rows.
// W1 read fully coalesced (float4), M staged in smem.
// ---------------------------------------------------------------------------
__global__ __launch_bounds__(384)
void k_center1(const float* __restrict__ M, const float* __restrict__ W1) {
    __shared__ float  sM[CEN][32];
    __shared__ float4 sAcc[4][CEN][D4];

    int tid = threadIdx.x;
    int hs  = tid / 96;          // h-split 0..3
    int d4  = tid % 96;
    int h0  = blockIdx.x * 32;

    if (tid < 320) {
        int c = tid / 32, hl = tid % 32;
        sM[c][hl] = __ldg(M + c * HID + h0 + hl);
    }
    __syncthreads();

    float4 acc[CEN];
#pragma unroll
    for (int c = 0; c < CEN; c++) acc[c] = make_float4(0.f, 0.f, 0.f, 0.f);

    const float4* W4 = (const float4*)W1;
#pragma unroll
    for (int i = 0; i < 8; i++) {
        int hl = hs * 8 + i;
        float4 w = __ldg(&W4[(size_t)(h0 + hl) * D4 + d4]);
#pragma unroll
        for (int c = 0; c < CEN; c++) {
            float m = sM[c][hl];
            acc[c].x += m * w.x;
            acc[c].y += m * w.y;
            acc[c].z += m * w.z;
            acc[c].w += m * w.w;
        }
    }
#pragma unroll
    for (int c = 0; c < CEN; c++) sAcc[hs][c][d4] = acc[c];
    __syncthreads();

    if (hs == 0) {
#pragma unroll
        for (int c = 0; c < CEN; c++) {
            float4 a = sAcc[0][c][d4], b = sAcc[1][c][d4];
            float4 e = sAcc[2][c][d4], f = sAcc[3][c][d4];
            float4 s;
            s.x = (a.x + b.x) + (e.x + f.x);
            s.y = (a.y + b.y) + (e.y + f.y);
            s.z = (a.z + b.z) + (e.z + f.z);
            s.w = (a.w + b.w) + (e.w + f.w);
            g_part4[((size_t)blockIdx.x * CEN + c) * D4 + d4] = s;
        }
    }
}

// ---------------------------------------------------------------------------
// K1b: reduce 24 partials + bias + LeakyReLU + /384. Also zero colsum.
// 3840 outputs; grid 15 x 256.
// ---------------------------------------------------------------------------
__global__ void k_center2(const float* __restrict__ b1) {
    int j = blockIdx.x * 256 + threadIdx.x;
    if (j < CEN * DIM) {
        const float* gp = (const float*)g_part4;
        float s = 0.f;
#pragma unroll
        for (int k = 0; k < 24; k++) s += gp[k * (CEN * DIM) + j];
        int d = j % DIM;
        float v = s + __ldg(b1 + d);
        v = (v >= 0.f) ? v : 0.01f * v;
        g_center[j] = v * (1.0f / 384.0f);
    }
    if (blockIdx.x == 0 && threadIdx.x < CEN) g_colsum[threadIdx.x] = 0.f;
}

// ---------------------------------------------------------------------------
// K2 (fused): phi + ct + colsum, packed f32x2 math.
// 256 threads = 8 warps; warp = 8 groups of 4 lanes; group owns one row.
// Lane q covers d4 = k*4+q (k=0..23). All vector data loaded as v2.u64.
// ---------------------------------------------------------------------------
__global__ __launch_bounds__(256)
void k_fused(const float* __restrict__ Ztd, float* __restrict__ out,
             const int* __restrict__ weighted) {
    __shared__ float4 sC[CEN * D4];
    __shared__ float  scn[CEN];
    __shared__ float  sred[8][CEN];

    int tid = threadIdx.x, lane = tid & 31, wid = tid >> 5;
    int q = lane & 3;
    int g = lane >> 2;

    const float4* gc4 = (const float4*)g_center;
    for (int i = tid; i < CEN * D4; i += 256) sC[i] = gc4[i];
    __syncthreads();

    for (int c = wid; c < CEN; c += 8) {
        float s = 0.f;
#pragma unroll
        for (int k = 0; k < 3; k++) {
            float4 v = sC[c * D4 + lane + 32 * k];
            s += v.x * v.x + v.y * v.y + v.z * v.z + v.w * v.w;
        }
#pragma unroll
        for (int o = 16; o; o >>= 1) s += __shfl_xor_sync(0xffffffffu, s, o);
        if (lane == 0) scn[c] = s;
    }
    __syncthreads();

    int row = blockIdx.x * 64 + wid * 8 + g;
    size_t zbase = (size_t)row * D4 + q;           // in 16B units
    const char* Zb = (const char*)Ztd;
    const ulonglong2* sC2 = (const ulonglong2*)sC;

    unsigned long long dp2[CEN], zz2 = 0ull;
#pragma unroll
    for (int c = 0; c < CEN; c++) dp2[c] = 0ull;

#pragma unroll 4
    for (int k = 0; k < 24; k++) {
        unsigned long long za, zb;
        asm("ld.global.cs.v2.u64 {%0, %1}, [%2];"
            : "=l"(za), "=l"(zb) : "l"(Zb + (zbase + k * 4) * 16));
        FMA2(zz2, za, za, zz2);
        FMA2(zz2, zb, zb, zz2);
#pragma unroll
        for (int c = 0; c < CEN; c++) {
            ulonglong2 cv = sC2[c * D4 + k * 4 + q];
            FMA2(dp2[c], za, cv.x, dp2[c]);
            FMA2(dp2[c], zb, cv.y, dp2[c]);
        }
    }

    float zz = upk_sum(zz2);
    float dp[CEN];
#pragma unroll
    for (int c = 0; c < CEN; c++) dp[c] = upk_sum(dp2[c]);

    // reduce across the 4 lanes of the group
#pragma unroll
    for (int o = 1; o <= 2; o <<= 1) {
        zz += __shfl_xor_sync(0xffffffffu, zz, o);
#pragma unroll
        for (int c = 0; c < CEN; c++)
            dp[c] += __shfl_xor_sync(0xffffffffu, dp[c], o);
    }

    float nu[CEN], den = 0.f;
#pragma unroll
    for (int c = 0; c < CEN; c++) {
        float n = zz - 2.f * dp[c] + scn[c];
        nu[c] = __fdividef(1.f, 1.f + n);
        den += nu[c];
    }
    float inv = __fdividef(1.f, den);
    float phi[CEN];
#pragma unroll
    for (int c = 0; c < CEN; c++) phi[c] = nu[c] * inv;

    // phi row (40B)
    {
        float2* p2 = (float2*)(out + PHI_OFF + (size_t)row * CEN);
        p2[q] = make_float2(phi[2 * q], phi[2 * q + 1]);
        if (q == 0) p2[4] = make_float2(phi[8], phi[9]);
    }

    // ct segment
    char* Cb = (char*)out;
    int w = *weighted;
    if (w) {
        unsigned long long pp[CEN];
#pragma unroll
        for (int c = 0; c < CEN; c++) pp[c] = pk2(phi[c], phi[c]);
#pragma unroll 4
        for (int k = 0; k < 24; k++) {
            unsigned long long a0 = 0ull, a1 = 0ull;
#pragma unroll
            for (int c = 0; c < CEN; c++) {
                ulonglong2 cv = sC2[c * D4 + k * 4 + q];
                FMA2(a0, pp[c], cv.x, a0);
                FMA2(a1, pp[c], cv.y, a1);
            }
            asm volatile("st.global.cs.v2.u64 [%0], {%1, %2};"
                         :: "l"(Cb + (zbase + k * 4) * 16), "l"(a0), "l"(a1)
                         : "memory");
        }
    } else {
        int am = 0; float bm = phi[0];
#pragma unroll
        for (int c = 1; c < CEN; c++)
            if (phi[c] > bm) { bm = phi[c]; am = c; }
#pragma unroll 4
        for (int k = 0; k < 24; k++) {
            ulonglong2 cv = sC2[am * D4 + k * 4 + q];
            asm volatile("st.global.cs.v2.u64 [%0], {%1, %2};"
                         :: "l"(Cb + (zbase + k * 4) * 16), "l"(cv.x), "l"(cv.y)
                         : "memory");
        }
    }

    // colsum
#pragma unroll
    for (int o = 4; o <= 16; o <<= 1) {
#pragma unroll
        for (int c = 0; c < CEN; c++)
            phi[c] += __shfl_xor_sync(0xffffffffu, phi[c], o);
    }
    if (lane == 0) {
#pragma unroll
        for (int c = 0; c < CEN; c++) sred[wid][c] = phi[c];
    }
    __syncthreads();
    if (tid < CEN) {
        float s = 0.f;
#pragma unroll
        for (int wv = 0; wv < 8; wv++) s += sred[wv][tid];
        atomicAdd(&g_colsum[tid], s);
    }
}

// ---------------------------------------------------------------------------
// K3: cluster_target. Thread per 2 rows, float4 I/O.
// ---------------------------------------------------------------------------
__global__ void k_target(float* __restrict__ out) {
    int t = blockIdx.x * 256 + threadIdx.x;
    if (t >= BATCH / 2) return;

    float cs[CEN];
#pragma unroll
    for (int c = 0; c < CEN; c++) cs[c] = g_colsum[c] + 1e-9f;

    const float4* p4 = (const float4*)(out + PHI_OFF + (size_t)t * 2 * CEN);
    float4 v[5];
#pragma unroll
    for (int i = 0; i < 5; i++) v[i] = __ldg(&p4[i]);
    float ph[20];
#pragma unroll
    for (int i = 0; i < 5; i++) {
        ph[4 * i + 0] = v[i].x; ph[4 * i + 1] = v[i].y;
        ph[4 * i + 2] = v[i].z; ph[4 * i + 3] = v[i].w;
    }

    float wv[20];
    float s0 = 0.f, s1 = 0.f;
#pragma unroll
    for (int c = 0; c < CEN; c++) {
        wv[c] = __fdividef(ph[c] * ph[c], cs[c]);
        s0 += wv[c];
        wv[10 + c] = __fdividef(ph[10 + c] * ph[10 + c], cs[c]);
        s1 += wv[10 + c];
    }
    float i0 = __fdividef(1.f, s0), i1 = __fdividef(1.f, s1);
#pragma unroll
    for (int c = 0; c < CEN; c++) { wv[c] *= i0; wv[10 + c] *= i1; }

    float4* o4 = (float4*)(out + TGT_OFF + (size_t)t * 2 * CEN);
#pragma unroll
    for (int i = 0; i < 5; i++)
        o4[i] = make_float4(wv[4 * i], wv[4 * i + 1], wv[4 * i + 2], wv[4 * i + 3]);
}

// ---------------------------------------------------------------------------
extern "C" void kernel_launch(void* const* d_in, const int* in_sizes, int n_in,
                              void* d_out, int out_size) {
    const float* Ztd = (const float*)d_in[0];
    const float* M   = (const float*)d_in[1];
    const float* W1  = (const float*)d_in[2];
    const float* b1  = (const float*)d_in[3];
    const int*   wfl = (const int*)d_in[4];
    float* out = (float*)d_out;

    k_center1<<<24, 384>>>(M, W1);
    k_center2<<<15, 256>>>(b1);
    k_fused<<<1024, 256>>>(Ztd, out, wfl);
    k_target<<<128, 256>>>(out);
}

// round 4
// speedup vs baseline: 2.9664x; 1.0823x over previous
#include <cuda_runtime.h>

#define BATCH 65536
#define CEN   10
#define DIM   384
#define HID   768
#define D4    96

#define PHI_OFF ((size_t)BATCH * DIM)
#define TGT_OFF ((size_t)BATCH * DIM + (size_t)BATCH * CEN)

__device__ float  g_center[CEN * DIM];
__device__ float  g_colsum[CEN];
__device__ float4 g_part4[24 * CEN * D4];

// packed f32x2 helpers
#define FMA2(d, a, b, c_) \
    asm("fma.rn.f32x2 %0, %1, %2, %3;" : "=l"(d) : "l"(a), "l"(b), "l"(c_))
__device__ __forceinline__ unsigned long long pk2(float a, float b) {
    unsigned long long r;
    asm("mov.b64 %0, {%1, %2};" : "=l"(r) : "f"(a), "f"(b));
    return r;
}
__device__ __forceinline__ float upk_sum(unsigned long long v) {
    float lo, hi;
    asm("mov.b64 {%0, %1}, %2;" : "=f"(lo), "=f"(hi) : "l"(v));
    return lo + hi;
}

// ---------------------------------------------------------------------------
// K1a: split-K partial GEMM for Center. 24 blocks x 384 threads.
// ---------------------------------------------------------------------------
__global__ __launch_bounds__(384)
void k_center1(const float* __restrict__ M, const float* __restrict__ W1) {
    __shared__ float  sM[CEN][32];
    __shared__ float4 sAcc[4][CEN][D4];

    int tid = threadIdx.x;
    int hs  = tid / 96;
    int d4  = tid % 96;
    int h0  = blockIdx.x * 32;

    if (tid < 320) {
        int c = tid / 32, hl = tid % 32;
        sM[c][hl] = __ldg(M + c * HID + h0 + hl);
    }
    __syncthreads();

    float4 acc[CEN];
#pragma unroll
    for (int c = 0; c < CEN; c++) acc[c] = make_float4(0.f, 0.f, 0.f, 0.f);

    const float4* W4 = (const float4*)W1;
#pragma unroll
    for (int i = 0; i < 8; i++) {
        int hl = hs * 8 + i;
        float4 w = __ldg(&W4[(size_t)(h0 + hl) * D4 + d4]);
#pragma unroll
        for (int c = 0; c < CEN; c++) {
            float m = sM[c][hl];
            acc[c].x += m * w.x; acc[c].y += m * w.y;
            acc[c].z += m * w.z; acc[c].w += m * w.w;
        }
    }
#pragma unroll
    for (int c = 0; c < CEN; c++) sAcc[hs][c][d4] = acc[c];
    __syncthreads();

    if (hs == 0) {
#pragma unroll
        for (int c = 0; c < CEN; c++) {
            float4 a = sAcc[0][c][d4], b = sAcc[1][c][d4];
            float4 e = sAcc[2][c][d4], f = sAcc[3][c][d4];
            float4 s;
            s.x = (a.x + b.x) + (e.x + f.x);
            s.y = (a.y + b.y) + (e.y + f.y);
            s.z = (a.z + b.z) + (e.z + f.z);
            s.w = (a.w + b.w) + (e.w + f.w);
            g_part4[((size_t)blockIdx.x * CEN + c) * D4 + d4] = s;
        }
    }
}

// ---------------------------------------------------------------------------
// K1b: reduce partials + bias + LeakyReLU + /384; zero colsum.
// ---------------------------------------------------------------------------
__global__ void k_center2(const float* __restrict__ b1) {
    int j = blockIdx.x * 256 + threadIdx.x;
    if (j < CEN * DIM) {
        const float* gp = (const float*)g_part4;
        float s = 0.f;
#pragma unroll
        for (int k = 0; k < 24; k++) s += gp[k * (CEN * DIM) + j];
        int d = j % DIM;
        float v = s + __ldg(b1 + d);
        v = (v >= 0.f) ? v : 0.01f * v;
        g_center[j] = v * (1.0f / 384.0f);
    }
    if (blockIdx.x == 0 && threadIdx.x < CEN) g_colsum[threadIdx.x] = 0.f;
}

// ---------------------------------------------------------------------------
// K2: phi + colsum. Block 128 = 4 warps. Warp: q = lane&3 owns d-quarter,
// group g = lane>>2; each thread processes R=4 rows (one center LDS serves 4
// rows). Block covers 128 rows; grid 512 -> 65536 rows, one pass.
// ---------------------------------------------------------------------------
__global__ __launch_bounds__(128)
void k_phi(const float* __restrict__ Ztd, float* __restrict__ out) {
    __shared__ float4 sC[CEN * D4];
    __shared__ float  scn[CEN];
    __shared__ float  sred[4][CEN];

    int tid = threadIdx.x, lane = tid & 31, wid = tid >> 5;
    int q = lane & 3;
    int g = lane >> 2;

    const float4* gc4 = (const float4*)g_center;
    for (int i = tid; i < CEN * D4; i += 128) sC[i] = gc4[i];
    __syncthreads();

    for (int c = wid; c < CEN; c += 4) {
        float s = 0.f;
#pragma unroll
        for (int k = 0; k < 3; k++) {
            float4 v = sC[c * D4 + lane + 32 * k];
            s += v.x * v.x + v.y * v.y + v.z * v.z + v.w * v.w;
        }
#pragma unroll
        for (int o = 16; o; o >>= 1) s += __shfl_xor_sync(0xffffffffu, s, o);
        if (lane == 0) scn[c] = s;
    }
    __syncthreads();

    int row0 = blockIdx.x * 128 + wid * 32 + g * 4;
    const char* Zb = (const char*)Ztd;
    const char* pr0 = Zb + ((size_t)(row0 + 0) * D4 + q) * 16;
    const char* pr1 = Zb + ((size_t)(row0 + 1) * D4 + q) * 16;
    const char* pr2 = Zb + ((size_t)(row0 + 2) * D4 + q) * 16;
    const char* pr3 = Zb + ((size_t)(row0 + 3) * D4 + q) * 16;
    const ulonglong2* sC2 = (const ulonglong2*)sC;

    unsigned long long dp2[4][CEN];
    unsigned long long zz2[4];
#pragma unroll
    for (int r = 0; r < 4; r++) {
        zz2[r] = 0ull;
#pragma unroll
        for (int c = 0; c < CEN; c++) dp2[r][c] = 0ull;
    }

#pragma unroll 4
    for (int k = 0; k < 24; k++) {
        unsigned long long za[4], zb[4];
        asm("ld.global.cs.v2.u64 {%0, %1}, [%2];" : "=l"(za[0]), "=l"(zb[0]) : "l"(pr0 + k * 64));
        asm("ld.global.cs.v2.u64 {%0, %1}, [%2];" : "=l"(za[1]), "=l"(zb[1]) : "l"(pr1 + k * 64));
        asm("ld.global.cs.v2.u64 {%0, %1}, [%2];" : "=l"(za[2]), "=l"(zb[2]) : "l"(pr2 + k * 64));
        asm("ld.global.cs.v2.u64 {%0, %1}, [%2];" : "=l"(za[3]), "=l"(zb[3]) : "l"(pr3 + k * 64));
#pragma unroll
        for (int r = 0; r < 4; r++) {
            FMA2(zz2[r], za[r], za[r], zz2[r]);
            FMA2(zz2[r], zb[r], zb[r], zz2[r]);
        }
#pragma unroll
        for (int c = 0; c < CEN; c++) {
            ulonglong2 cv = sC2[c * D4 + k * 4 + q];
#pragma unroll
            for (int r = 0; r < 4; r++) {
                FMA2(dp2[r][c], za[r], cv.x, dp2[r][c]);
                FMA2(dp2[r][c], zb[r], cv.y, dp2[r][c]);
            }
        }
    }

    float zz[4], dp[4][CEN];
#pragma unroll
    for (int r = 0; r < 4; r++) {
        zz[r] = upk_sum(zz2[r]);
#pragma unroll
        for (int c = 0; c < CEN; c++) dp[r][c] = upk_sum(dp2[r][c]);
    }

    // reduce over the 4 q-lanes of the group
#pragma unroll
    for (int o = 1; o <= 2; o <<= 1) {
#pragma unroll
        for (int r = 0; r < 4; r++) {
            zz[r] += __shfl_xor_sync(0xffffffffu, zz[r], o);
#pragma unroll
            for (int c = 0; c < CEN; c++)
                dp[r][c] += __shfl_xor_sync(0xffffffffu, dp[r][c], o);
        }
    }

    float colAcc[CEN];
#pragma unroll
    for (int c = 0; c < CEN; c++) colAcc[c] = 0.f;

#pragma unroll
    for (int r = 0; r < 4; r++) {
        float nu[CEN], den = 0.f;
#pragma unroll
        for (int c = 0; c < CEN; c++) {
            float n = zz[r] - 2.f * dp[r][c] + scn[c];
            nu[c] = __fdividef(1.f, 1.f + n);
            den += nu[c];
        }
        float inv = __fdividef(1.f, den);
        float phi[CEN];
#pragma unroll
        for (int c = 0; c < CEN; c++) {
            phi[c] = nu[c] * inv;
            colAcc[c] += phi[c];
        }
        float2* p2 = (float2*)(out + PHI_OFF + (size_t)(row0 + r) * CEN);
        p2[q] = make_float2(phi[2 * q], phi[2 * q + 1]);
        if (q == 0) p2[4] = make_float2(phi[8], phi[9]);
    }

    // colsum: all 4 lanes of a group hold identical colAcc; reduce groups,
    // divide by 4 at the end.
#pragma unroll
    for (int o = 4; o <= 16; o <<= 1) {
#pragma unroll
        for (int c = 0; c < CEN; c++)
            colAcc[c] += __shfl_xor_sync(0xffffffffu, colAcc[c], o);
    }
    if (lane == 0) {
#pragma unroll
        for (int c = 0; c < CEN; c++) sred[wid][c] = colAcc[c];
    }
    __syncthreads();
    if (tid < CEN) {
        float s = 0.f;
#pragma unroll
        for (int w = 0; w < 4; w++) s += sred[w][tid];
        atomicAdd(&g_colsum[tid], s);
    }
}

// ---------------------------------------------------------------------------
// K3: ct = phi @ Center (centers in REGISTERS, no smem) + fused target.
// Block 384 = 4 row-groups x 96 d4-threads. Grid 1024, 16 row-iters each.
// Thread tid%96==0 also emits the target row for its group's row.
// ---------------------------------------------------------------------------
__global__ __launch_bounds__(384)
void k_ct(float* __restrict__ out, const int* __restrict__ weighted) {
    int tid = threadIdx.x;
    int grp = tid / 96;           // 0..3 (warp-uniform: 96 = 3 warps)
    int d4  = tid % 96;
    int w   = *weighted;
    bool tlane = (d4 == 0);

    ulonglong2 cv[CEN];
    const ulonglong2* gc2 = (const ulonglong2*)g_center;
#pragma unroll
    for (int c = 0; c < CEN; c++) cv[c] = __ldg(&gc2[c * D4 + d4]);

    float cs[CEN];
    if (tlane) {
#pragma unroll
        for (int c = 0; c < CEN; c++) cs[c] = g_colsum[c] + 1e-9f;
    }

    const float* phiG = out + PHI_OFF;
    char* Cb = (char*)out;

    for (int it = 0; it < 16; it++) {
        int row = blockIdx.x * 64 + it * 4 + grp;

        const float2* p2 = (const float2*)(phiG + (size_t)row * CEN);
        float ph[CEN];
        float2 t;
        t = __ldg(p2 + 0); ph[0] = t.x; ph[1] = t.y;
        t = __ldg(p2 + 1); ph[2] = t.x; ph[3] = t.y;
        t = __ldg(p2 + 2); ph[4] = t.x; ph[5] = t.y;
        t = __ldg(p2 + 3); ph[6] = t.x; ph[7] = t.y;
        t = __ldg(p2 + 4); ph[8] = t.x; ph[9] = t.y;

        unsigned long long a0, a1;
        if (w) {
            a0 = 0ull; a1 = 0ull;
#pragma unroll
            for (int c = 0; c < CEN; c++) {
                unsigned long long pp = pk2(ph[c], ph[c]);
                FMA2(a0, pp, cv[c].x, a0);
                FMA2(a1, pp, cv[c].y, a1);
            }
        } else {
            int am = 0; float bm = ph[0];
#pragma unroll
            for (int c = 1; c < CEN; c++)
                if (ph[c] > bm) { bm = ph[c]; am = c; }
            a0 = cv[0].x; a1 = cv[0].y;
#pragma unroll
            for (int c = 1; c < CEN; c++)
                if (am == c) { a0 = cv[c].x; a1 = cv[c].y; }
        }
        asm volatile("st.global.cs.v2.u64 [%0], {%1, %2};"
                     :: "l"(Cb + ((size_t)row * D4 + d4) * 16), "l"(a0), "l"(a1)
                     : "memory");

        if (tlane) {
            float wv[CEN], s = 0.f;
#pragma unroll
            for (int c = 0; c < CEN; c++) {
                wv[c] = __fdividef(ph[c] * ph[c], cs[c]);
                s += wv[c];
            }
            float inv = __fdividef(1.f, s);
            float2* o2 = (float2*)(out + TGT_OFF + (size_t)row * CEN);
#pragma unroll
            for (int i = 0; i < 5; i++)
                o2[i] = make_float2(wv[2 * i] * inv, wv[2 * i + 1] * inv);
        }
    }
}

// ---------------------------------------------------------------------------
extern "C" void kernel_launch(void* const* d_in, const int* in_sizes, int n_in,
                              void* d_out, int out_size) {
    const float* Ztd = (const float*)d_in[0];
    const float* M   = (const float*)d_in[1];
    const float* W1  = (const float*)d_in[2];
    const float* b1  = (const float*)d_in[3];
    const int*   wfl = (const int*)d_in[4];
    float* out = (float*)d_out;

    k_center1<<<24, 384>>>(M, W1);
    k_center2<<<15, 256>>>(b1);
    k_phi<<<512, 128>>>(Ztd, out);
    k_ct<<<1024, 384>>>(out, wfl);
}